// round 3
// baseline (speedup 1.0000x reference)
#include <cuda_runtime.h>
#include <cstdint>

#define Tn 2048
#define Bn 256
#define Hn 128

// Scratch for layer-0 hidden states h1[B][T][H] (256 MB, static device array)
__device__ float g_h1[(size_t)Bn * Tn * Hn];

__device__ __forceinline__ uint32_t smem_u32(const void* p) {
    return (uint32_t)__cvta_generic_to_shared(p);
}
__device__ __forceinline__ void cluster_sync_() {
    asm volatile("barrier.cluster.arrive.aligned;" ::: "memory");
    asm volatile("barrier.cluster.wait.aligned;" ::: "memory");
}
__device__ __forceinline__ uint32_t mapa_sh(uint32_t addr, uint32_t rank) {
    uint32_t r;
    asm("mapa.shared::cluster.u32 %0, %1, %2;" : "=r"(r) : "r"(addr), "r"(rank));
    return r;
}
__device__ __forceinline__ void st_dsmem(uint32_t addr, float v) {
    asm volatile("st.shared::cluster.f32 [%0], %1;" :: "r"(addr), "f"(v) : "memory");
}
__device__ __forceinline__ float sigm(float v) { return 1.0f / (1.0f + __expf(-v)); }
__device__ __forceinline__ float tanh_(float v) { return 2.0f / (1.0f + __expf(-2.0f * v)) - 1.0f; }

// ---------------------------------------------------------------------------
// Layer 0: cluster of 2 CTAs, each CTA owns hidden slice of 64 (x4 gates =
// 256 W_hh rows, smem-resident). 4 batch rows per cluster. 64 clusters = 128 CTAs.
// smem layout (floats):
//   Wsl  [256][132]   0
//   Wx   [256][9]     33792
//   bias [256]        36096
//   hbuf [2][4][128]  36352
//   xbuf [2][4][8]    37376
//   gbuf [256][4]     37440
//   total             38464 floats = 153856 B
// ---------------------------------------------------------------------------
#define SMEM0_BYTES (38464 * 4)

__global__ void __cluster_dims__(2, 1, 1) __launch_bounds__(256, 1)
lstm_layer0(const float* __restrict__ x, const float* __restrict__ Wih,
            const float* __restrict__ Whh, const float* __restrict__ bih,
            const float* __restrict__ bhh)
{
    extern __shared__ float sm[];
    float* Wsl  = sm;
    float* Wx   = sm + 33792;
    float* bias = sm + 36096;
    float* hbuf = sm + 36352;
    float* xbuf = sm + 37376;
    float* gbuf = sm + 37440;

    const int tid  = threadIdx.x;
    const int rank = blockIdx.x & 1;
    const int b0   = (blockIdx.x >> 1) * 4;

    // Load W_hh slice: gate-slice rows (4 gates x 64 hidden), padded pitch 132
    for (int idx = tid; idx < 256 * 128; idx += 256) {
        int r = idx >> 7, k = idx & 127;
        int grow = ((r >> 6) << 7) + (rank << 6) + (r & 63);
        Wsl[r * 132 + k] = Whh[grow * 128 + k];
    }
    {
        int r = tid;
        int grow = ((r >> 6) << 7) + (rank << 6) + (r & 63);
        bias[r] = bih[grow] + bhh[grow];
        #pragma unroll
        for (int d = 0; d < 5; ++d) Wx[r * 9 + d] = Wih[grow * 5 + d];
    }
    for (int i = tid; i < 2 * 4 * 128; i += 256) hbuf[i] = 0.f;
    if (tid < 20) {
        int b = tid / 5, d = tid % 5;
        xbuf[b * 8 + d] = x[((size_t)(b0 + b) * Tn + 0) * 5 + d];
    }

    const int cb = tid >> 6, cj = tid & 63;   // combine mapping: batch, hidden idx
    // Precompute DSMEM addresses (self + peer) for both write parities
    uint32_t wr_addr[2][2];
    #pragma unroll
    for (int nbv = 0; nbv < 2; ++nbv) {
        int off = nbv * 512 + cb * 128 + (rank << 6) + cj;
        uint32_t la = smem_u32(hbuf + off);
        wr_addr[nbv][0] = mapa_sh(la, 0);
        wr_addr[nbv][1] = mapa_sh(la, 1);
    }
    float c = 0.f;
    __syncthreads();
    cluster_sync_();

    for (int t = 0; t < Tn; ++t) {
        const int par = t & 1, nb = par ^ 1;
        float pre = 0.f;
        if (tid < 20 && t + 1 < Tn) {
            int b = tid / 5, d = tid % 5;
            pre = x[((size_t)(b0 + b) * Tn + (t + 1)) * 5 + d];
        }
        // gates = bias + W_ih x_t + W_hh h_{t-1}; thread = one gate row, 4 batches
        float bb = bias[tid];
        float a0 = bb, a1 = bb, a2 = bb, a3 = bb;
        {
            const float* xb = xbuf + par * 32;
            #pragma unroll
            for (int d = 0; d < 5; ++d) {
                float w = Wx[tid * 9 + d];
                a0 = fmaf(w, xb[d], a0);
                a1 = fmaf(w, xb[8 + d], a1);
                a2 = fmaf(w, xb[16 + d], a2);
                a3 = fmaf(w, xb[24 + d], a3);
            }
        }
        const float*  hp = hbuf + par * 512;
        const float4* wr = (const float4*)(Wsl + tid * 132);
        #pragma unroll
        for (int kk = 0; kk < 32; ++kk) {
            float4 w  = wr[kk];
            float4 h0 = *(const float4*)(hp + kk * 4);
            float4 h1 = *(const float4*)(hp + 128 + kk * 4);
            float4 h2 = *(const float4*)(hp + 256 + kk * 4);
            float4 h3 = *(const float4*)(hp + 384 + kk * 4);
            a0 = fmaf(w.x, h0.x, fmaf(w.y, h0.y, fmaf(w.z, h0.z, fmaf(w.w, h0.w, a0))));
            a1 = fmaf(w.x, h1.x, fmaf(w.y, h1.y, fmaf(w.z, h1.z, fmaf(w.w, h1.w, a1))));
            a2 = fmaf(w.x, h2.x, fmaf(w.y, h2.y, fmaf(w.z, h2.z, fmaf(w.w, h2.w, a2))));
            a3 = fmaf(w.x, h3.x, fmaf(w.y, h3.y, fmaf(w.z, h3.z, fmaf(w.w, h3.w, a3))));
        }
        *(float4*)(gbuf + tid * 4) = make_float4(a0, a1, a2, a3);
        if (tid < 20 && t + 1 < Tn) {
            int b = tid / 5, d = tid % 5;
            xbuf[nb * 32 + b * 8 + d] = pre;
        }
        __syncthreads();
        // combine: thread = (batch cb, hidden cj)
        float gi = gbuf[cj * 4 + cb];
        float gf = gbuf[(64 + cj) * 4 + cb];
        float gg = gbuf[(128 + cj) * 4 + cb];
        float go = gbuf[(192 + cj) * 4 + cb];
        float ii = sigm(gi), ff = sigm(gf), g = tanh_(gg), oo = sigm(go);
        c = fmaf(ff, c, ii * g);
        float h = oo * tanh_(c);
        st_dsmem(wr_addr[nb][0], h);
        st_dsmem(wr_addr[nb][1], h);
        g_h1[(((size_t)(b0 + cb) * Tn + t) << 7) + (rank << 6) + cj] = h;
        cluster_sync_();
    }
}

// ---------------------------------------------------------------------------
// Layer 1 + FC head: cluster of 4 CTAs, each CTA owns hidden slice of 32
// (4 gates x 32 = 128 rows of BOTH W_ih1 and W_hh1 in smem). 8 batch rows per
// cluster. 32 clusters = 128 CTAs. h1_t prefetched from g_h1 one step ahead.
// smem layout (floats):
//   Wi   [128][132]   0
//   Wh   [128][132]   16896
//   bias [128]        33792
//   hbuf [2][8][128]  33920
//   sbuf [2][8][128]  35968
//   gbuf [128][12]    38016
//   total             39552 floats = 158208 B
// ---------------------------------------------------------------------------
#define SMEM1_BYTES (39552 * 4)

__global__ void __cluster_dims__(4, 1, 1) __launch_bounds__(256, 1)
lstm_layer1(const float* __restrict__ Wih, const float* __restrict__ Whh,
            const float* __restrict__ bih, const float* __restrict__ bhh,
            const float* __restrict__ fcW, const float* __restrict__ fcb,
            float* __restrict__ out)
{
    extern __shared__ float sm[];
    float* Wi   = sm;
    float* Wh   = sm + 16896;
    float* bias = sm + 33792;
    float* hbuf = sm + 33920;
    float* sbuf = sm + 35968;
    float* gbuf = sm + 38016;

    const int tid  = threadIdx.x;
    const int rank = blockIdx.x & 3;
    const int b0   = (blockIdx.x >> 2) * 8;

    for (int idx = tid; idx < 128 * 128; idx += 256) {
        int r = idx >> 7, k = idx & 127;
        int grow = ((r >> 5) << 7) + (rank << 5) + (r & 31);
        Wi[r * 132 + k] = Wih[grow * 128 + k];
        Wh[r * 132 + k] = Whh[grow * 128 + k];
    }
    if (tid < 128) {
        int grow = ((tid >> 5) << 7) + (rank << 5) + (tid & 31);
        bias[tid] = bih[grow] + bhh[grow];
    }
    for (int i = tid; i < 2048; i += 256) hbuf[i] = 0.f;

    const int sb = tid >> 5, sq = tid & 31;   // h1 staging map (coalesced float4)
    {
        float4 v = *(const float4*)(g_h1 + (((size_t)(b0 + sb) * Tn + 0) << 7) + sq * 4);
        *(float4*)(sbuf + sb * 128 + sq * 4) = v;
    }
    const int row = tid & 127, bh = tid >> 7; // gate row, batch-half
    const int cb = tid >> 5, cj = tid & 31;   // combine: batch, hidden idx
    uint32_t wr_addr[2][4];
    #pragma unroll
    for (int nbv = 0; nbv < 2; ++nbv) {
        int off = nbv * 1024 + cb * 128 + (rank << 5) + cj;
        uint32_t la = smem_u32(hbuf + off);
        #pragma unroll
        for (int r = 0; r < 4; ++r) wr_addr[nbv][r] = mapa_sh(la, r);
    }
    float c = 0.f;
    __syncthreads();
    cluster_sync_();

    for (int t = 0; t < Tn; ++t) {
        const int par = t & 1, nb = par ^ 1;
        float4 pre = make_float4(0.f, 0.f, 0.f, 0.f);
        if (t + 1 < Tn)
            pre = *(const float4*)(g_h1 + (((size_t)(b0 + sb) * Tn + (t + 1)) << 7) + sq * 4);

        float bb = bias[row];
        float a0 = bb, a1 = bb, a2 = bb, a3 = bb;
        const float*  sp = sbuf + par * 1024 + bh * 512;  // h1_t (4 batches)
        const float*  hp = hbuf + par * 1024 + bh * 512;  // h2_{t-1}
        const float4* wi = (const float4*)(Wi + row * 132);
        const float4* wh = (const float4*)(Wh + row * 132);
        #pragma unroll
        for (int kk = 0; kk < 32; ++kk) {
            float4 w  = wi[kk];
            float4 h0 = *(const float4*)(sp + kk * 4);
            float4 h1 = *(const float4*)(sp + 128 + kk * 4);
            float4 h2 = *(const float4*)(sp + 256 + kk * 4);
            float4 h3 = *(const float4*)(sp + 384 + kk * 4);
            a0 = fmaf(w.x, h0.x, fmaf(w.y, h0.y, fmaf(w.z, h0.z, fmaf(w.w, h0.w, a0))));
            a1 = fmaf(w.x, h1.x, fmaf(w.y, h1.y, fmaf(w.z, h1.z, fmaf(w.w, h1.w, a1))));
            a2 = fmaf(w.x, h2.x, fmaf(w.y, h2.y, fmaf(w.z, h2.z, fmaf(w.w, h2.w, a2))));
            a3 = fmaf(w.x, h3.x, fmaf(w.y, h3.y, fmaf(w.z, h3.z, fmaf(w.w, h3.w, a3))));
        }
        #pragma unroll
        for (int kk = 0; kk < 32; ++kk) {
            float4 w  = wh[kk];
            float4 h0 = *(const float4*)(hp + kk * 4);
            float4 h1 = *(const float4*)(hp + 128 + kk * 4);
            float4 h2 = *(const float4*)(hp + 256 + kk * 4);
            float4 h3 = *(const float4*)(hp + 384 + kk * 4);
            a0 = fmaf(w.x, h0.x, fmaf(w.y, h0.y, fmaf(w.z, h0.z, fmaf(w.w, h0.w, a0))));
            a1 = fmaf(w.x, h1.x, fmaf(w.y, h1.y, fmaf(w.z, h1.z, fmaf(w.w, h1.w, a1))));
            a2 = fmaf(w.x, h2.x, fmaf(w.y, h2.y, fmaf(w.z, h2.z, fmaf(w.w, h2.w, a2))));
            a3 = fmaf(w.x, h3.x, fmaf(w.y, h3.y, fmaf(w.z, h3.z, fmaf(w.w, h3.w, a3))));
        }
        *(float4*)(gbuf + row * 12 + bh * 4) = make_float4(a0, a1, a2, a3);
        if (t + 1 < Tn) *(float4*)(sbuf + nb * 1024 + sb * 128 + sq * 4) = pre;
        __syncthreads();

        float gi = gbuf[cj * 12 + cb];
        float gf = gbuf[(32 + cj) * 12 + cb];
        float gg = gbuf[(64 + cj) * 12 + cb];
        float go = gbuf[(96 + cj) * 12 + cb];
        float ii = sigm(gi), ff = sigm(gf), g = tanh_(gg), oo = sigm(go);
        c = fmaf(ff, c, ii * g);
        float h = oo * tanh_(c);
        #pragma unroll
        for (int r = 0; r < 4; ++r) st_dsmem(wr_addr[nb][r], h);
        cluster_sync_();
    }

    // FC head: full h2_T (buffer 0, since T is even) lives in every CTA's hbuf.
    if (rank == 0 && tid < 16) {
        int b = tid >> 1, cl = tid & 1;
        const float* hT = hbuf + b * 128;
        float s = fcb[cl];
        #pragma unroll
        for (int j = 0; j < 128; ++j) s = fmaf(hT[j], fcW[cl * 128 + j], s);
        out[(b0 + b) * 2 + cl] = s;
    }
}

// ---------------------------------------------------------------------------
extern "C" void kernel_launch(void* const* d_in, const int* in_sizes, int n_in,
                              void* d_out, int out_size)
{
    const float* x    = (const float*)d_in[0];
    const float* Wih0 = (const float*)d_in[1];
    const float* Whh0 = (const float*)d_in[2];
    const float* bih0 = (const float*)d_in[3];
    const float* bhh0 = (const float*)d_in[4];
    const float* Wih1 = (const float*)d_in[5];
    const float* Whh1 = (const float*)d_in[6];
    const float* bih1 = (const float*)d_in[7];
    const float* bhh1 = (const float*)d_in[8];
    const float* fcW  = (const float*)d_in[9];
    const float* fcb  = (const float*)d_in[10];
    float* out = (float*)d_out;

    cudaFuncSetAttribute(lstm_layer0, cudaFuncAttributeMaxDynamicSharedMemorySize, SMEM0_BYTES);
    cudaFuncSetAttribute(lstm_layer1, cudaFuncAttributeMaxDynamicSharedMemorySize, SMEM1_BYTES);

    lstm_layer0<<<128, 256, SMEM0_BYTES>>>(x, Wih0, Whh0, bih0, bhh0);
    lstm_layer1<<<128, 256, SMEM1_BYTES>>>(Wih1, Whh1, bih1, bhh1, fcW, fcb, out);
}

// round 4
// speedup vs baseline: 1.1716x; 1.1716x over previous
#include <cuda_runtime.h>
#include <cstdint>

#define Tn 2048
#define Bn 256
#define Hn 128

// Scratch for layer-0 hidden states h1[B][T][H] (256 MB, static device array)
__device__ float g_h1[(size_t)Bn * Tn * Hn];

__device__ __forceinline__ uint32_t smem_u32(const void* p) {
    return (uint32_t)__cvta_generic_to_shared(p);
}
__device__ __forceinline__ void cluster_sync_() {
    asm volatile("barrier.cluster.arrive.aligned;" ::: "memory");
    asm volatile("barrier.cluster.wait.aligned;" ::: "memory");
}
__device__ __forceinline__ uint32_t mapa_sh(uint32_t addr, uint32_t rank) {
    uint32_t r;
    asm("mapa.shared::cluster.u32 %0, %1, %2;" : "=r"(r) : "r"(addr), "r"(rank));
    return r;
}
__device__ __forceinline__ void st_dsmem(uint32_t addr, float v) {
    asm volatile("st.shared::cluster.f32 [%0], %1;" :: "r"(addr), "f"(v) : "memory");
}
__device__ __forceinline__ float sigm(float v) { return 1.0f / (1.0f + __expf(-v)); }
__device__ __forceinline__ float tanh_(float v) { return 2.0f / (1.0f + __expf(-2.0f * v)) - 1.0f; }

// ---------------------------------------------------------------------------
// Layer 0: cluster of 2 CTAs, each CTA owns hidden slice of 64 (x4 gates =
// 256 gate rows). W_hh row (128 f) + W_ih row (5 f) REGISTER-RESIDENT per
// thread. 4 batch rows per cluster. 64 clusters = 128 CTAs.
// smem (floats): hbuf [2][4][128] @0 (1024), xbuf [2][4][8] @1024 (64),
//                gbuf [256][5]    @1088 (1280)  -> total 2368 f = 9472 B
// ---------------------------------------------------------------------------
#define SMEM0_BYTES (2368 * 4)

__global__ void __cluster_dims__(2, 1, 1) __launch_bounds__(256, 1)
lstm_layer0(const float* __restrict__ x, const float* __restrict__ Wih,
            const float* __restrict__ Whh, const float* __restrict__ bih,
            const float* __restrict__ bhh)
{
    extern __shared__ float sm[];
    float* hbuf = sm;          // [2][4][128]
    float* xbuf = sm + 1024;   // [2][4][8]
    float* gbuf = sm + 1088;   // [256][5]

    const int tid  = threadIdx.x;
    const int rank = blockIdx.x & 1;
    const int b0   = (blockIdx.x >> 1) * 4;

    // This thread's gate row (global): gate = tid>>6, hidden = rank*64 + (tid&63)
    const int grow = ((tid >> 6) << 7) + (rank << 6) + (tid & 63);

    // Register-resident weights
    float4 w4[32];
    {
        const float4* wsrc = (const float4*)(Whh + grow * 128);
        #pragma unroll
        for (int kk = 0; kk < 32; ++kk) w4[kk] = wsrc[kk];
    }
    float wx[5];
    #pragma unroll
    for (int d = 0; d < 5; ++d) wx[d] = Wih[grow * 5 + d];
    const float bb = bih[grow] + bhh[grow];

    for (int i = tid; i < 1024; i += 256) hbuf[i] = 0.f;
    if (tid < 20) {
        int b = tid / 5, d = tid % 5;
        xbuf[b * 8 + d] = x[((size_t)(b0 + b) * Tn) * 5 + d];
    }

    const int cb = tid >> 6, cj = tid & 63;   // combine: batch, hidden idx
    uint32_t wr_addr[2][2];
    #pragma unroll
    for (int nbv = 0; nbv < 2; ++nbv) {
        int off = nbv * 512 + cb * 128 + (rank << 6) + cj;
        uint32_t la = smem_u32(hbuf + off);
        wr_addr[nbv][0] = mapa_sh(la, 0);
        wr_addr[nbv][1] = mapa_sh(la, 1);
    }
    float c = 0.f;
    __syncthreads();
    cluster_sync_();

    for (int t = 0; t < Tn; ++t) {
        const int par = t & 1, nb = par ^ 1;
        float pre = 0.f;
        if (tid < 20 && t + 1 < Tn) {
            int b = tid / 5, d = tid % 5;
            pre = x[((size_t)(b0 + b) * Tn + (t + 1)) * 5 + d];
        }
        float a0 = bb, a1 = bb, a2 = bb, a3 = bb;
        {
            const float* xb = xbuf + par * 32;
            #pragma unroll
            for (int d = 0; d < 5; ++d) {
                a0 = fmaf(wx[d], xb[d], a0);
                a1 = fmaf(wx[d], xb[8 + d], a1);
                a2 = fmaf(wx[d], xb[16 + d], a2);
                a3 = fmaf(wx[d], xb[24 + d], a3);
            }
        }
        const float* hp = hbuf + par * 512;
        #pragma unroll
        for (int kk = 0; kk < 32; ++kk) {
            float4 w  = w4[kk];
            float4 h0 = *(const float4*)(hp + kk * 4);
            float4 h1 = *(const float4*)(hp + 128 + kk * 4);
            float4 h2 = *(const float4*)(hp + 256 + kk * 4);
            float4 h3 = *(const float4*)(hp + 384 + kk * 4);
            a0 = fmaf(w.x, h0.x, fmaf(w.y, h0.y, fmaf(w.z, h0.z, fmaf(w.w, h0.w, a0))));
            a1 = fmaf(w.x, h1.x, fmaf(w.y, h1.y, fmaf(w.z, h1.z, fmaf(w.w, h1.w, a1))));
            a2 = fmaf(w.x, h2.x, fmaf(w.y, h2.y, fmaf(w.z, h2.z, fmaf(w.w, h2.w, a2))));
            a3 = fmaf(w.x, h3.x, fmaf(w.y, h3.y, fmaf(w.z, h3.z, fmaf(w.w, h3.w, a3))));
        }
        // pitch-5 gate buffer: writes stride 5 (odd) -> conflict-free
        gbuf[tid * 5 + 0] = a0;
        gbuf[tid * 5 + 1] = a1;
        gbuf[tid * 5 + 2] = a2;
        gbuf[tid * 5 + 3] = a3;
        if (tid < 20 && t + 1 < Tn) {
            int b = tid / 5, d = tid % 5;
            xbuf[nb * 32 + b * 8 + d] = pre;
        }
        __syncthreads();
        // combine: thread = (batch cb, hidden cj)
        float gi = gbuf[cj * 5 + cb];
        float gf = gbuf[(64 + cj) * 5 + cb];
        float gg = gbuf[(128 + cj) * 5 + cb];
        float go = gbuf[(192 + cj) * 5 + cb];
        float ii = sigm(gi), ff = sigm(gf), g = tanh_(gg), oo = sigm(go);
        c = fmaf(ff, c, ii * g);
        float h = oo * tanh_(c);
        st_dsmem(wr_addr[nb][0], h);
        st_dsmem(wr_addr[nb][1], h);
        g_h1[(((size_t)(b0 + cb) * Tn + t) << 7) + (rank << 6) + cj] = h;
        cluster_sync_();
    }
}

// ---------------------------------------------------------------------------
// Layer 1 + FC head: cluster of 4 CTAs, each CTA owns hidden slice of 32
// (4 gates x 32 = 128 gate rows). Thread = (row 0-127, K-half): half 0 holds
// the W_ih1 row in registers and contracts h1_t; half 1 holds the W_hh1 row
// and contracts h2_{t-1}. 8-batch partial accumulators; partials summed in
// the combine phase. 8 batch rows per cluster. 32 clusters = 128 CTAs.
// smem (floats): hbuf [2][8][128] @0 (2048), sbuf [2][8][128] @2048 (2048),
//                gbuf [2][128][9] @4096 (2304) -> total 6400 f = 25600 B
// ---------------------------------------------------------------------------
#define SMEM1_BYTES (6400 * 4)

__global__ void __cluster_dims__(4, 1, 1) __launch_bounds__(256, 1)
lstm_layer1(const float* __restrict__ Wih, const float* __restrict__ Whh,
            const float* __restrict__ bih, const float* __restrict__ bhh,
            const float* __restrict__ fcW, const float* __restrict__ fcb,
            float* __restrict__ out)
{
    extern __shared__ float sm[];
    float* hbuf = sm;          // [2][8][128] h2 state (DSMEM-exchanged)
    float* sbuf = sm + 2048;   // [2][8][128] h1_t staging (prefetched)
    float* gbuf = sm + 4096;   // [2][128][9] gate partials (half, row, batch)

    const int tid  = threadIdx.x;
    const int rank = blockIdx.x & 3;
    const int b0   = (blockIdx.x >> 2) * 8;

    const int row  = tid & 127;          // local gate row
    const int half = tid >> 7;           // 0: W_ih (h1 input), 1: W_hh (h2 recur)
    const int grow = ((row >> 5) << 7) + (rank << 5) + (row & 31);

    // Register-resident weight row (Wih for half 0, Whh for half 1)
    float4 w4[32];
    {
        const float4* wsrc = (const float4*)(((half == 0) ? Wih : Whh) + grow * 128);
        #pragma unroll
        for (int kk = 0; kk < 32; ++kk) w4[kk] = wsrc[kk];
    }
    const float bb = (half == 0) ? (bih[grow] + bhh[grow]) : 0.f;

    for (int i = tid; i < 2048; i += 256) hbuf[i] = 0.f;

    const int sb = tid >> 5, sq = tid & 31;   // h1 staging map (coalesced float4)
    {
        float4 v = *(const float4*)(g_h1 + (((size_t)(b0 + sb) * Tn) << 7) + sq * 4);
        *(float4*)(sbuf + sb * 128 + sq * 4) = v;
    }
    const int cb = tid >> 5, cj = tid & 31;   // combine: batch, hidden idx
    uint32_t wr_addr[2][4];
    #pragma unroll
    for (int nbv = 0; nbv < 2; ++nbv) {
        int off = nbv * 1024 + cb * 128 + (rank << 5) + cj;
        uint32_t la = smem_u32(hbuf + off);
        #pragma unroll
        for (int r = 0; r < 4; ++r) wr_addr[nbv][r] = mapa_sh(la, r);
    }
    float c = 0.f;
    __syncthreads();
    cluster_sync_();

    for (int t = 0; t < Tn; ++t) {
        const int par = t & 1, nb = par ^ 1;
        float4 pre = make_float4(0.f, 0.f, 0.f, 0.f);
        if (t + 1 < Tn)
            pre = *(const float4*)(g_h1 + (((size_t)(b0 + sb) * Tn + (t + 1)) << 7) + sq * 4);

        float a[8];
        #pragma unroll
        for (int b = 0; b < 8; ++b) a[b] = bb;

        const float* src = ((half == 0) ? sbuf : hbuf) + par * 1024;
        #pragma unroll
        for (int kk = 0; kk < 32; ++kk) {
            float4 w = w4[kk];
            #pragma unroll
            for (int b = 0; b < 8; ++b) {
                float4 h = *(const float4*)(src + b * 128 + kk * 4);
                a[b] = fmaf(w.x, h.x, fmaf(w.y, h.y, fmaf(w.z, h.z, fmaf(w.w, h.w, a[b]))));
            }
        }
        // partial-sum buffer, pitch 9 (odd) -> conflict-free scalar access
        #pragma unroll
        for (int b = 0; b < 8; ++b) gbuf[half * 1152 + row * 9 + b] = a[b];

        if (t + 1 < Tn) *(float4*)(sbuf + nb * 1024 + sb * 128 + sq * 4) = pre;
        __syncthreads();

        float gi = gbuf[cj * 9 + cb]          + gbuf[1152 + cj * 9 + cb];
        float gf = gbuf[(32 + cj) * 9 + cb]   + gbuf[1152 + (32 + cj) * 9 + cb];
        float gg = gbuf[(64 + cj) * 9 + cb]   + gbuf[1152 + (64 + cj) * 9 + cb];
        float go = gbuf[(96 + cj) * 9 + cb]   + gbuf[1152 + (96 + cj) * 9 + cb];
        float ii = sigm(gi), ff = sigm(gf), g = tanh_(gg), oo = sigm(go);
        c = fmaf(ff, c, ii * g);
        float h = oo * tanh_(c);
        #pragma unroll
        for (int r = 0; r < 4; ++r) st_dsmem(wr_addr[nb][r], h);
        cluster_sync_();
    }

    // FC head: full h2_T (buffer 0, since T is even) lives in every CTA's hbuf.
    if (rank == 0 && tid < 16) {
        int b = tid >> 1, cl = tid & 1;
        const float* hT = hbuf + b * 128;
        float s = fcb[cl];
        #pragma unroll
        for (int j = 0; j < 128; ++j) s = fmaf(hT[j], fcW[cl * 128 + j], s);
        out[(b0 + b) * 2 + cl] = s;
    }
}

// ---------------------------------------------------------------------------
extern "C" void kernel_launch(void* const* d_in, const int* in_sizes, int n_in,
                              void* d_out, int out_size)
{
    const float* x    = (const float*)d_in[0];
    const float* Wih0 = (const float*)d_in[1];
    const float* Whh0 = (const float*)d_in[2];
    const float* bih0 = (const float*)d_in[3];
    const float* bhh0 = (const float*)d_in[4];
    const float* Wih1 = (const float*)d_in[5];
    const float* Whh1 = (const float*)d_in[6];
    const float* bih1 = (const float*)d_in[7];
    const float* bhh1 = (const float*)d_in[8];
    const float* fcW  = (const float*)d_in[9];
    const float* fcb  = (const float*)d_in[10];
    float* out = (float*)d_out;

    lstm_layer0<<<128, 256, SMEM0_BYTES>>>(x, Wih0, Whh0, bih0, bhh0);
    lstm_layer1<<<128, 256, SMEM1_BYTES>>>(Wih1, Whh1, bih1, bhh1, fcW, fcb, out);
}